// round 1
// baseline (speedup 1.0000x reference)
#include <cuda_runtime.h>
#include <math.h>

#define TT 512
#define BB 64
#define II 512
#define HH 512
#define G4 2048            // 4*HH
#define NCTA 128           // persistent CTAs (<=148 SMs, 1 per SM)
#define A_STRIDE 516       // padded row stride for a_sh (conflict-free float4)

// ---------------- scratch (static device globals; no allocs allowed) -------
__device__ float g_xw[(size_t)TT * BB * G4];   // 256 MB: x@W + b, [T*B, 4H]
__device__ float g_a[2][BB * HH];              // double-buffered hidden state
__device__ unsigned int g_bar_count = 0;
__device__ volatile unsigned int g_bar_gen = 0;

// ---------------- phase 1: xW = x @ W + b  (M=32768, N=2048, K=512) --------
__global__ void __launch_bounds__(256) xw_gemm_kernel(
    const float* __restrict__ X,      // [T*B, I] row-major
    const float* __restrict__ W,      // [I, 4H] row-major
    const float* __restrict__ bias)   // [4H]
{
    __shared__ float As[8][128];      // transposed A tile
    __shared__ float Bs[8][128];

    const int tid = threadIdx.x;
    const int m0 = blockIdx.y * 128;
    const int n0 = blockIdx.x * 128;
    const int ty = tid >> 4;          // 0..15
    const int tx = tid & 15;          // 0..15

    // load mapping
    const int ar = tid >> 1;          // 0..127 row of A tile
    const int ac = (tid & 1) * 4;     // 0 or 4 (k within tile)
    const int br = tid >> 5;          // 0..7 row (k) of B tile
    const int bc = (tid & 31) * 4;    // col of B tile

    float acc[8][8];
#pragma unroll
    for (int i = 0; i < 8; i++)
#pragma unroll
        for (int j = 0; j < 8; j++) acc[i][j] = 0.f;

    for (int k0 = 0; k0 < II; k0 += 8) {
        float4 av = *(const float4*)&X[(size_t)(m0 + ar) * II + k0 + ac];
        As[ac + 0][ar] = av.x;
        As[ac + 1][ar] = av.y;
        As[ac + 2][ar] = av.z;
        As[ac + 3][ar] = av.w;
        *(float4*)&Bs[br][bc] = *(const float4*)&W[(size_t)(k0 + br) * G4 + n0 + bc];
        __syncthreads();

#pragma unroll
        for (int k = 0; k < 8; k++) {
            float ra[8], rb[8];
#pragma unroll
            for (int i = 0; i < 8; i++) ra[i] = As[k][ty * 8 + i];
#pragma unroll
            for (int j = 0; j < 8; j++) rb[j] = Bs[k][tx * 8 + j];
#pragma unroll
            for (int i = 0; i < 8; i++)
#pragma unroll
                for (int j = 0; j < 8; j++) acc[i][j] += ra[i] * rb[j];
        }
        __syncthreads();
    }

    float bv[8];
#pragma unroll
    for (int j = 0; j < 8; j++) bv[j] = bias[n0 + tx * 8 + j];

#pragma unroll
    for (int i = 0; i < 8; i++) {
        float* orow = &g_xw[(size_t)(m0 + ty * 8 + i) * G4 + n0 + tx * 8];
#pragma unroll
        for (int j = 0; j < 8; j++) orow[j] = acc[i][j] + bv[j];
    }
}

// ---------------- phase 2: recurrent persistent kernel ---------------------
__device__ __forceinline__ void grid_barrier()
{
    __syncthreads();
    if (threadIdx.x == 0) {
        __threadfence();
        unsigned int g = g_bar_gen;
        if (atomicAdd(&g_bar_count, 1u) == NCTA - 1) {
            g_bar_count = 0;
            __threadfence();
            g_bar_gen = g + 1;
        } else {
            while (g_bar_gen == g) { }
        }
        __threadfence();
    }
    __syncthreads();
}

__device__ __forceinline__ float sigmoidf_(float x)
{
    return 1.0f / (1.0f + expf(-x));
}

extern __shared__ float dyn_smem[];

__global__ void __launch_bounds__(256) rnn_kernel(
    const float* __restrict__ a0,     // [B, H]
    const float* __restrict__ U,      // [H, 4H]
    float* __restrict__ out)          // [T, B, H]
{
    float*  a_sh = dyn_smem;                                   // [BB][A_STRIDE]
    float4* Us4  = (float4*)(dyn_smem + BB * A_STRIDE);        // [HH][4] gate-quads

    const int tid = threadIdx.x;
    const int cta = blockIdx.x;
    const int hc0 = cta * 4;          // this CTA owns h columns hc0..hc0+3
    const int b   = tid >> 2;         // 0..63
    const int hc  = tid & 3;          // 0..3
    const int col = hc0 + hc;

    // Load resident U slice: Us4[k*4+j] = {U[k][j+hc0], U[k][H+j+hc0], U[k][2H+..], U[k][3H+..]}
    for (int idx = tid; idx < HH * 4; idx += 256) {
        int k = idx >> 2, j = idx & 3;
        float4 v;
        v.x = U[(size_t)k * G4 + 0 * HH + hc0 + j];
        v.y = U[(size_t)k * G4 + 1 * HH + hc0 + j];
        v.z = U[(size_t)k * G4 + 2 * HH + hc0 + j];
        v.w = U[(size_t)k * G4 + 3 * HH + hc0 + j];
        Us4[idx] = v;
    }

    // init hidden-state buffer 0 from a0 (exactly 128*256 = 32768 threads)
    {
        int gid = cta * 256 + tid;
        g_a[0][gid] = a0[gid];
    }
    grid_barrier();

    int cur = 0;
    for (int t = 0; t < TT; ++t) {
        // stage full a_{t-1} into shared (padded rows)
        const float* a_cur = g_a[cur];
        for (int idx = tid; idx < BB * (HH / 4); idx += 256) {
            int bb = idx >> 7;            // idx / 128
            int k4 = (idx & 127) << 2;    // 4-float chunk
            *(float4*)&a_sh[bb * A_STRIDE + k4] =
                *(const float4*)&a_cur[bb * HH + k4];
        }
        __syncthreads();

        // accumulators start from precomputed xW + b
        const float* xwrow = &g_xw[((size_t)t * BB + b) * G4 + col];
        float acc0 = xwrow[0 * HH];
        float acc1 = xwrow[1 * HH];
        float acc2 = xwrow[2 * HH];
        float acc3 = xwrow[3 * HH];

        const float* arow = &a_sh[b * A_STRIDE];
#pragma unroll 4
        for (int k = 0; k < HH; k += 4) {
            float4 av = *(const float4*)&arow[k];
            float4 u0 = Us4[(k + 0) * 4 + hc];
            float4 u1 = Us4[(k + 1) * 4 + hc];
            float4 u2 = Us4[(k + 2) * 4 + hc];
            float4 u3 = Us4[(k + 3) * 4 + hc];
            acc0 += av.x * u0.x; acc1 += av.x * u0.y; acc2 += av.x * u0.z; acc3 += av.x * u0.w;
            acc0 += av.y * u1.x; acc1 += av.y * u1.y; acc2 += av.y * u1.z; acc3 += av.y * u1.w;
            acc0 += av.z * u2.x; acc1 += av.z * u2.y; acc2 += av.z * u2.z; acc3 += av.z * u2.w;
            acc0 += av.w * u3.x; acc1 += av.w * u3.y; acc2 += av.w * u3.z; acc3 += av.w * u3.w;
        }

        float gu   = sigmoidf_(acc0);
        float gf   = sigmoidf_(acc1);
        float go   = sigmoidf_(acc2);
        float cand = tanhf(acc3);
        float aprev = a_sh[b * A_STRIDE + col];  // forget gate hits previous hidden
        float c  = gu * cand + gf * aprev;
        float av = go * tanhf(c);

        g_a[1 - cur][b * HH + col] = av;
        out[((size_t)t * BB + b) * HH + col] = av;

        grid_barrier();     // publishes a_{t}; separates buffer reuse
        cur ^= 1;
    }
}

// ---------------- launch ----------------------------------------------------
extern "C" void kernel_launch(void* const* d_in, const int* in_sizes, int n_in,
                              void* d_out, int out_size)
{
    const float* x  = (const float*)d_in[0];   // [T, B, I]
    const float* a0 = (const float*)d_in[1];   // [B, H]
    const float* W  = (const float*)d_in[2];   // [I, 4H]
    const float* U  = (const float*)d_in[3];   // [H, 4H]
    const float* bb = (const float*)d_in[4];   // [4H]
    float* out = (float*)d_out;

    // phase 1: xW = x@W + b
    dim3 g1(G4 / 128, (TT * BB) / 128);
    xw_gemm_kernel<<<g1, 256>>>(x, W, bb);

    // phase 2: persistent recurrence
    const int smem_bytes = (BB * A_STRIDE + HH * 4 * 4) * (int)sizeof(float); // 164864
    static int attr_set = 0;
    cudaFuncSetAttribute(rnn_kernel, cudaFuncAttributeMaxDynamicSharedMemorySize, smem_bytes);
    (void)attr_set;
    rnn_kernel<<<NCTA, 256, smem_bytes>>>(a0, U, out);
}

// round 2
// speedup vs baseline: 1.2017x; 1.2017x over previous
#include <cuda_runtime.h>
#include <math.h>

#define TT 512
#define BB 64
#define II 512
#define HH 512
#define G4 2048
#define NCTA 128
#define A_STRIDE 516          // floats; stride bytes = 2064 ≡ 16 (mod 128) -> conflict-free float4
#define SPAD 18               // ull padding for partials (16B aligned rows, spread banks)

typedef unsigned long long ull;

// ---------------- scratch ----------------------------------------------------
__device__ float g_xw[(size_t)TT * BB * G4];   // x@W + b
__device__ float g_a[2][BB * HH];
__device__ unsigned int g_bar_count = 0;
__device__ volatile unsigned int g_bar_gen = 0;

// ---------------- f32x2 helpers ----------------------------------------------
#define FMA2(d, a, b, c) \
    asm("fma.rn.f32x2 %0, %1, %2, %3;" : "=l"(d) : "l"(a), "l"(b), "l"(c))
#define ADD2(d, a, b) \
    asm("add.rn.f32x2 %0, %1, %2;" : "=l"(d) : "l"(a), "l"(b))

__device__ __forceinline__ ull packf2(float lo, float hi) {
    return (ull)__float_as_uint(lo) | ((ull)__float_as_uint(hi) << 32);
}
__device__ __forceinline__ float sum2(ull v) {
    return __uint_as_float((unsigned)v) + __uint_as_float((unsigned)(v >> 32));
}

// ---------------- phase 1: xW = x@W + b (M=32768, N=2048, K=512) -------------
// 128x128x8 tile, 8x8 microtile, k-paired FFMA2 accumulators.
__global__ void __launch_bounds__(256, 1) xw_gemm_kernel(
    const float* __restrict__ X,
    const float* __restrict__ W,
    const float* __restrict__ bias)
{
    __shared__ ull As2[4 * 128];   // [kpair][row]   pair = (k even, k odd)
    __shared__ ull Bs2[4 * 128];   // [kpair][col]

    const int tid = threadIdx.x;
    const int m0 = blockIdx.y * 128;
    const int n0 = blockIdx.x * 128;
    const int ty = tid >> 4;
    const int tx = tid & 15;

    const int ar = tid >> 1;
    const int ac = (tid & 1) * 4;
    const int br = tid >> 5;
    const int bc = (tid & 31) * 4;

    ull acc[8][8];
#pragma unroll
    for (int i = 0; i < 8; i++)
#pragma unroll
        for (int j = 0; j < 8; j++) acc[i][j] = 0ull;

    for (int k0 = 0; k0 < II; k0 += 8) {
        float4 av = *(const float4*)&X[(size_t)(m0 + ar) * II + k0 + ac];
        float4 wv = *(const float4*)&W[(size_t)(k0 + br) * G4 + n0 + bc];

        As2[(ac >> 1) * 128 + ar]       = packf2(av.x, av.y);
        As2[((ac >> 1) + 1) * 128 + ar] = packf2(av.z, av.w);
        {
            float* Bsf = (float*)Bs2;
            int base = ((br >> 1) * 128 + bc) * 2 + (br & 1);
#pragma unroll
            for (int j = 0; j < 4; j++) Bsf[base + j * 2] = ((const float*)&wv)[j];
        }
        __syncthreads();

#pragma unroll
        for (int kk = 0; kk < 4; kk++) {
            ull ra[8], rb[8];
            const ulonglong2* ap = (const ulonglong2*)&As2[kk * 128 + ty * 8];
            const ulonglong2* bp = (const ulonglong2*)&Bs2[kk * 128 + tx * 8];
#pragma unroll
            for (int i = 0; i < 4; i++) { ulonglong2 v = ap[i]; ra[2*i] = v.x; ra[2*i+1] = v.y; }
#pragma unroll
            for (int j = 0; j < 4; j++) { ulonglong2 v = bp[j]; rb[2*j] = v.x; rb[2*j+1] = v.y; }
#pragma unroll
            for (int i = 0; i < 8; i++)
#pragma unroll
                for (int j = 0; j < 8; j++) FMA2(acc[i][j], ra[i], rb[j], acc[i][j]);
        }
        __syncthreads();
    }

    float bv[8];
#pragma unroll
    for (int j = 0; j < 8; j++) bv[j] = bias[n0 + tx * 8 + j];

#pragma unroll
    for (int i = 0; i < 8; i++) {
        float* orow = &g_xw[(size_t)(m0 + ty * 8 + i) * G4 + n0 + tx * 8];
#pragma unroll
        for (int j = 0; j < 8; j++) orow[j] = sum2(acc[i][j]) + bv[j];
    }
}

// ---------------- phase 2: persistent recurrence -----------------------------
__device__ __forceinline__ void grid_barrier()
{
    __syncthreads();
    if (threadIdx.x == 0) {
        __threadfence();
        unsigned int g = g_bar_gen;
        if (atomicAdd(&g_bar_count, 1u) == NCTA - 1) {
            g_bar_count = 0;
            __threadfence();
            g_bar_gen = g + 1;
        } else {
            while (g_bar_gen == g) { }
        }
        __threadfence();
    }
    __syncthreads();
}

__device__ __forceinline__ float sigmoidf_(float x) { return 1.0f / (1.0f + expf(-x)); }

extern __shared__ float dyn_smem[];

// smem: a_sh [64][A_STRIDE] floats | Up [256 kpairs][16 cols] ull | part [4][64][SPAD] ull
__global__ void __launch_bounds__(256) rnn_kernel(
    const float* __restrict__ a0,
    const float* __restrict__ U,
    float* __restrict__ out)
{
    float* a_sh = dyn_smem;
    ull*   Up   = (ull*)(dyn_smem + BB * A_STRIDE);
    ull*   part = Up + 256 * 16;

    const int tid  = threadIdx.x;
    const int cta  = blockIdx.x;
    const int hc0  = cta * 4;
    const int wid  = tid >> 5;
    const int lane = tid & 31;

    // compute-phase mapping: warp -> (bhalf, ksec); lane = batch within half
    const int bhalf = wid & 1;
    const int ksec  = wid >> 1;          // 0..3, 128 k each
    const int bW    = bhalf * 32 + lane;

    // activation-phase mapping
    const int bA = tid >> 2;
    const int hc = tid & 3;
    const int colA = hc0 + hc;

    // Build paired U slice: Up[kk*16 + cc] = (U[2kk][gcol], U[2kk+1][gcol]),
    // cc = gate*4 + j, gcol = gate*HH + hc0 + j
    for (int idx = tid; idx < 256 * 16; idx += 256) {
        int kk = idx >> 4, cc = idx & 15;
        int gcol = (cc >> 2) * HH + hc0 + (cc & 3);
        float lo = U[(size_t)(2 * kk) * G4 + gcol];
        float hi = U[(size_t)(2 * kk + 1) * G4 + gcol];
        Up[idx] = packf2(lo, hi);
    }

    { int gid = cta * 256 + tid; g_a[0][gid] = a0[gid]; }
    grid_barrier();

    int cur = 0;
    for (int t = 0; t < TT; ++t) {
        // stage a_{t-1}
        const float* a_cur = g_a[cur];
        for (int idx = tid; idx < BB * (HH / 4); idx += 256) {
            int bb = idx >> 7;
            int k4 = (idx & 127) << 2;
            *(float4*)&a_sh[bb * A_STRIDE + k4] = *(const float4*)&a_cur[bb * HH + k4];
        }

        // prefetch xW gate values (activation mapping) while staging completes
        const float* xwrow = &g_xw[((size_t)t * BB + bA) * G4 + colA];
        float xg0 = xwrow[0 * HH];
        float xg1 = xwrow[1 * HH];
        float xg2 = xwrow[2 * HH];
        float xg3 = xwrow[3 * HH];
        __syncthreads();

        // partial dot products: 16 gate-cols, k range [ksec*128, ksec*128+128)
        ull acc[16];
#pragma unroll
        for (int c = 0; c < 16; c++) acc[c] = 0ull;

        const float* ar = &a_sh[bW * A_STRIDE + ksec * 128];
        const ull*   ub = &Up[(ksec * 64) * 16];

#pragma unroll 2
        for (int kk = 0; kk < 64; kk += 2) {
            ulonglong2 av = *(const ulonglong2*)&ar[kk * 2];   // 2 k-pairs (4 k)
            const ulonglong2* u0 = (const ulonglong2*)&ub[kk * 16];
            const ulonglong2* u1 = (const ulonglong2*)&ub[(kk + 1) * 16];
#pragma unroll
            for (int c = 0; c < 8; c++) {
                ulonglong2 uv = u0[c];
                FMA2(acc[2 * c],     av.x, uv.x, acc[2 * c]);
                FMA2(acc[2 * c + 1], av.x, uv.y, acc[2 * c + 1]);
            }
#pragma unroll
            for (int c = 0; c < 8; c++) {
                ulonglong2 uv = u1[c];
                FMA2(acc[2 * c],     av.y, uv.x, acc[2 * c]);
                FMA2(acc[2 * c + 1], av.y, uv.y, acc[2 * c + 1]);
            }
        }

        // store partials
        {
            ull* p = &part[(ksec * 64 + bW) * SPAD];
#pragma unroll
            for (int c = 0; c < 16; c += 2)
                *(ulonglong2*)&p[c] = make_ulonglong2(acc[c], acc[c + 1]);
        }
        __syncthreads();

        // reduce + activations (thread = (bA, hc))
        float gsum[4];
#pragma unroll
        for (int g = 0; g < 4; g++) {
            int cc = g * 4 + hc;
            ull v0 = part[(0 * 64 + bA) * SPAD + cc];
            ull v1 = part[(1 * 64 + bA) * SPAD + cc];
            ull v2 = part[(2 * 64 + bA) * SPAD + cc];
            ull v3 = part[(3 * 64 + bA) * SPAD + cc];
            ull s01, s23, s;
            ADD2(s01, v0, v1);
            ADD2(s23, v2, v3);
            ADD2(s, s01, s23);
            gsum[g] = sum2(s);
        }

        float gu   = sigmoidf_(gsum[0] + xg0);
        float gf   = sigmoidf_(gsum[1] + xg1);
        float go   = sigmoidf_(gsum[2] + xg2);
        float cand = tanhf(gsum[3] + xg3);
        float aprev = a_sh[bA * A_STRIDE + colA];
        float c_t   = gu * cand + gf * aprev;
        float a_t   = go * tanhf(c_t);

        g_a[1 - cur][bA * HH + colA] = a_t;
        out[((size_t)t * BB + bA) * HH + colA] = a_t;

        grid_barrier();
        cur ^= 1;
    }
}

// ---------------- launch ------------------------------------------------------
extern "C" void kernel_launch(void* const* d_in, const int* in_sizes, int n_in,
                              void* d_out, int out_size)
{
    const float* x  = (const float*)d_in[0];
    const float* a0 = (const float*)d_in[1];
    const float* W  = (const float*)d_in[2];
    const float* U  = (const float*)d_in[3];
    const float* bb = (const float*)d_in[4];
    float* out = (float*)d_out;

    dim3 g1(G4 / 128, (TT * BB) / 128);
    xw_gemm_kernel<<<g1, 256>>>(x, W, bb);

    const int smem_bytes = BB * A_STRIDE * 4          // a_sh
                         + 256 * 16 * 8               // Up
                         + 4 * 64 * SPAD * 8;         // partials
    cudaFuncSetAttribute(rnn_kernel, cudaFuncAttributeMaxDynamicSharedMemorySize, smem_bytes);
    rnn_kernel<<<NCTA, 256, smem_bytes>>>(a0, U, out);
}